// round 9
// baseline (speedup 1.0000x reference)
#include <cuda_runtime.h>
#include <math.h>
#include <stdint.h>

#define Dm   1024
#define Hh   16
#define DKk  64
#define Bb   4
#define Ll   2048
#define MTOT (Bb * Ll)   // 8192

#define NPLANE ((size_t)MTOT * Dm)   // 8388608 elems
#define WPLANE ((size_t)Dm * Dm)     // 1048576

// One big bf16 scratch buffer (no allocations allowed): 240 MB
__device__ __align__(16) uint16_t g_buf[14 * NPLANE + 8 * WPLANE];

__device__ __forceinline__ uint32_t smem_u32(const void* p) {
    uint32_t a;
    asm("{ .reg .u64 t; cvta.to.shared.u64 t, %1; cvt.u32.u64 %0, t; }"
        : "=r"(a) : "l"(p));
    return a;
}

// Split two fp32 into packed bf16 hi-pair and lo-pair (x0 -> low half).
__device__ __forceinline__ void split2(float x0, float x1,
                                       uint32_t& hi, uint32_t& lo) {
    uint32_t h;
    asm("cvt.rn.bf16x2.f32 %0, %1, %2;" : "=r"(h) : "f"(x1), "f"(x0));
    const float f0 = __uint_as_float(h << 16);
    const float f1 = __uint_as_float(h & 0xffff0000u);
    uint32_t l;
    asm("cvt.rn.bf16x2.f32 %0, %1, %2;" : "=r"(l) : "f"(x1 - f1), "f"(x0 - f0));
    hi = h; lo = l;
}

__device__ __forceinline__ void mma_bf16(float d[4], const uint32_t a[4],
                                         const uint32_t b[2]) {
    asm volatile(
        "mma.sync.aligned.m16n8k16.row.col.f32.bf16.bf16.f32 "
        "{%0,%1,%2,%3}, {%4,%5,%6,%7}, {%8,%9}, {%0,%1,%2,%3};"
        : "+f"(d[0]), "+f"(d[1]), "+f"(d[2]), "+f"(d[3])
        : "r"(a[0]), "r"(a[1]), "r"(a[2]), "r"(a[3]), "r"(b[0]), "r"(b[1]));
}

__device__ __forceinline__ void ldsm_x4(uint32_t r[4], uint32_t a) {
    asm volatile("ldmatrix.sync.aligned.m8n8.x4.shared.b16 {%0,%1,%2,%3}, [%4];"
                 : "=r"(r[0]), "=r"(r[1]), "=r"(r[2]), "=r"(r[3]) : "r"(a));
}
__device__ __forceinline__ void ldsm_x4_t(uint32_t r[4], uint32_t a) {
    asm volatile("ldmatrix.sync.aligned.m8n8.x4.trans.shared.b16 {%0,%1,%2,%3}, [%4];"
                 : "=r"(r[0]), "=r"(r[1]), "=r"(r[2]), "=r"(r[3]) : "r"(a));
}

#define CP16(smaddr, gptr) \
    asm volatile("cp.async.cg.shared.global [%0], [%1], 16;" \
                 :: "r"(smaddr), "l"(gptr))
#define CP_COMMIT() asm volatile("cp.async.commit_group;")

// ---------------------------------------------------------------------------
// fp32 -> bf16 hi/lo plane split, up to 4 tensors per launch (blockIdx.y)
// ---------------------------------------------------------------------------
struct Split4 {
    const float* in[4];
    uint16_t* hi[4];
    uint16_t* lo[4];
};

__global__ __launch_bounds__(256)
void split_multi(Split4 a, int n8)
{
    const float* in = a.in[blockIdx.y];
    uint16_t* hi = a.hi[blockIdx.y];
    uint16_t* lo = a.lo[blockIdx.y];
    const int i = blockIdx.x * 256 + threadIdx.x;
    if (i < n8) {
        const float4* in4 = (const float4*)in;
        float4 x = in4[2 * i], y = in4[2 * i + 1];
        uint4 H, L;
        split2(x.x, x.y, H.x, L.x);
        split2(x.z, x.w, H.y, L.y);
        split2(y.x, y.y, H.z, L.z);
        split2(y.z, y.w, H.w, L.w);
        ((uint4*)hi)[i] = H;
        ((uint4*)lo)[i] = L;
    }
}

// ---------------------------------------------------------------------------
// split-bf16 GEMM (batched over blockIdx.z): C = A @ W^T + bias.
// 256 thr / 8 warps (2m x 4n), warp 64x32, KCH=16, 4-stage cp.async pipeline,
// ONE __syncthreads per chunk. smem rows 48 B -> conflict-free ldmatrix.
// ---------------------------------------------------------------------------
#define GK      1024
#define GN      1024
#define KCH     16
#define NCHUNK  (GK / KCH)             // 64
#define GROWB   48                     // bytes per smem row
#define GPLANEB (128 * GROWB)          // 6144 B per plane
#define GSTAGEB (4 * GPLANEB)          // 24576 B (Ahi,Alo,Bhi,Blo)
#define GEMM_SMEM_BYTES (4 * GSTAGEB)  // 98304 B

struct GemmJob {
    const uint16_t *Ah, *Al, *Bh, *Bl;
    const float* bias;
    float* Cf;           // fp32 output (or null)
    uint16_t *Ch, *Cl;   // bf16 plane outputs (if Cf null)
    float scale;
};
struct GemmBatch { GemmJob j[3]; };

__global__ __launch_bounds__(256, 2)
void gemm_bf16s(GemmBatch batch)
{
    extern __shared__ uint32_t smu[];
    const GemmJob jb = batch.j[blockIdx.z];

    const int tid  = threadIdx.x;
    const int warp = tid >> 5;
    const int lane = tid & 31;
    const int wm   = warp & 1;
    const int wn   = warp >> 1;        // 0..3
    const int m0   = blockIdx.y * 128;
    const int n0   = blockIdx.x * 128;
    const int frow = tid >> 1;         // 0..127
    const int fseg = tid & 1;          // 0..1

    const uint32_t smub = smem_u32(smu);
    const uint32_t aoff = (uint32_t)(((lane & 7) + ((lane >> 3) & 1) * 8) * GROWB +
                                     ((lane >> 4) << 4));
    const uint32_t boff = (uint32_t)(((lane & 7) + ((lane >> 4) << 3)) * GROWB +
                                     (((lane >> 3) & 1) << 4));

    float d[4][4][4];
    #pragma unroll
    for (int mi = 0; mi < 4; mi++)
        #pragma unroll
        for (int ni = 0; ni < 4; ni++)
            #pragma unroll
            for (int x = 0; x < 4; x++) d[mi][ni][x] = 0.f;

    auto fill = [&](int c) {
        const int k0 = c * KCH;
        const uint32_t base = smub + (c & 3) * GSTAGEB;
        const uint32_t so = (uint32_t)(frow * GROWB + fseg * 16);
        const size_t ga = (size_t)(m0 + frow) * GK + k0 + fseg * 8;
        const size_t gb = (size_t)(n0 + frow) * GK + k0 + fseg * 8;
        CP16(base + 0 * GPLANEB + so, jb.Ah + ga);
        CP16(base + 1 * GPLANEB + so, jb.Al + ga);
        CP16(base + 2 * GPLANEB + so, jb.Bh + gb);
        CP16(base + 3 * GPLANEB + so, jb.Bl + gb);
        CP_COMMIT();
    };

    fill(0); fill(1); fill(2);

    for (int c = 0; c < NCHUNK; c++) {
        if (c) __syncthreads();
        if (c + 3 < NCHUNK) fill(c + 3);
        else CP_COMMIT();
        asm volatile("cp.async.wait_group 3;" ::: "memory");
        if (!c) __syncthreads();

        const uint32_t stB = smub + (c & 3) * GSTAGEB;
        const uint32_t aA  = stB + (uint32_t)(wm * 64 * GROWB) + aoff;
        const uint32_t aB  = stB + 2 * GPLANEB + (uint32_t)(wn * 32 * GROWB) + boff;

        uint32_t ah[4][4], bh[2][4], bl[2][4];
        #pragma unroll
        for (int mi = 0; mi < 4; mi++)
            ldsm_x4(ah[mi], aA + mi * 16 * GROWB);
        #pragma unroll
        for (int p = 0; p < 2; p++)
            ldsm_x4(bh[p], aB + p * 16 * GROWB);
        // product 1: Ah*Bh
        #pragma unroll
        for (int mi = 0; mi < 4; mi++)
            #pragma unroll
            for (int p = 0; p < 2; p++) {
                mma_bf16(d[mi][2 * p],     ah[mi], &bh[p][0]);
                mma_bf16(d[mi][2 * p + 1], ah[mi], &bh[p][2]);
            }
        // product 2: Ah*Bl
        #pragma unroll
        for (int p = 0; p < 2; p++)
            ldsm_x4(bl[p], aB + GPLANEB + p * 16 * GROWB);
        #pragma unroll
        for (int mi = 0; mi < 4; mi++)
            #pragma unroll
            for (int p = 0; p < 2; p++) {
                mma_bf16(d[mi][2 * p],     ah[mi], &bl[p][0]);
                mma_bf16(d[mi][2 * p + 1], ah[mi], &bl[p][2]);
            }
        // product 3: Al*Bh (reuse ah regs)
        #pragma unroll
        for (int mi = 0; mi < 4; mi++)
            ldsm_x4(ah[mi], aA + GPLANEB + mi * 16 * GROWB);
        #pragma unroll
        for (int mi = 0; mi < 4; mi++)
            #pragma unroll
            for (int p = 0; p < 2; p++) {
                mma_bf16(d[mi][2 * p],     ah[mi], &bh[p][0]);
                mma_bf16(d[mi][2 * p + 1], ah[mi], &bh[p][2]);
            }
    }

    const int row0 = m0 + wm * 64 + (lane >> 2);
    const int colb = n0 + wn * 32 + 2 * (lane & 3);
    #pragma unroll
    for (int ni = 0; ni < 4; ni++) {
        const int c = colb + ni * 8;
        const float b0 = jb.bias[c], b1 = jb.bias[c + 1];
        #pragma unroll
        for (int mi = 0; mi < 4; mi++) {
            #pragma unroll
            for (int half = 0; half < 2; half++) {
                const int r = row0 + mi * 16 + 8 * half;
                const float v0 = d[mi][ni][2 * half]     + b0;
                const float v1 = d[mi][ni][2 * half + 1] + b1;
                if (jb.Cf) {
                    float2 w = {v0, v1};
                    *(float2*)(jb.Cf + (size_t)r * GN + c) = w;
                } else {
                    uint32_t hv, lv;
                    split2(v0 * jb.scale, v1 * jb.scale, hv, lv);
                    ((uint32_t*)jb.Ch)[(size_t)r * (GN / 2) + c / 2] = hv;
                    ((uint32_t*)jb.Cl)[(size_t)r * (GN / 2) + c / 2] = lv;
                }
            }
        }
    }
}

// ---------------------------------------------------------------------------
// Flash attention (causal), split-bf16 MMAs. P kept in registers (S C-frag
// layout == PV A-frag layout). 3-stage KV pipeline, one sync per iteration.
// smem: 3 KV stages x (Kh,Kl,Vh,Vl @ 64x144B); Q staged in stage 2.
// ---------------------------------------------------------------------------
#define AST     36                  // u32 per row (144 B)
#define APL     (64 * AST)          // KV plane u32 (2304)
#define ASTG    (4 * APL)           // stage u32 (9216)
#define AQPL    (128 * AST)         // Q plane u32 (4608)
#define ATT_SMEM_BYTES (3 * ASTG * 4)   // 110592

__global__ __launch_bounds__(256, 2)
void attn_bf16s(const uint16_t* __restrict__ Qh, const uint16_t* __restrict__ Ql,
                const uint16_t* __restrict__ Kh, const uint16_t* __restrict__ Kl,
                const uint16_t* __restrict__ Vh, const uint16_t* __restrict__ Vl,
                uint16_t* __restrict__ Ch, uint16_t* __restrict__ Cl)
{
    extern __shared__ uint32_t smu[];
    const int tid  = threadIdx.x;
    const int lane = tid & 31;
    const int warp = tid >> 5;
    const int r    = lane >> 2;
    const int cth  = lane & 3;
    const int qi   = gridDim.x - 1 - blockIdx.x;   // heavy tiles first
    const int hd   = blockIdx.y;
    const int b    = blockIdx.z;
    const int q0   = qi * 128;

    const uint32_t smub = smem_u32(smu);
    const size_t hoff = (size_t)hd * 64;

    const uint32_t koff = (uint32_t)(((lane & 7) + ((lane >> 4) << 3)) * 144 +
                                     (((lane >> 3) & 1) << 4));
    const uint32_t voff = (uint32_t)((lane & 15) * 144 + ((lane >> 4) << 4));

    // Prologue: Q planes into stage-2 area (group 0)
    #pragma unroll
    for (int i = 0; i < 4; i++) {
        const int id  = tid + i * 256;       // 0..1023
        const int row = id >> 3, seg = id & 7;
        const uint32_t so = (uint32_t)(row * 144 + seg * 16);
        const size_t g = ((size_t)(b * Ll + q0 + row)) * Dm + hoff + seg * 8;
        CP16(smub + 2 * ASTG * 4 + so, Qh + g);
        CP16(smub + 2 * ASTG * 4 + AQPL * 4 + so, Ql + g);
    }
    CP_COMMIT();

    auto fillKV = [&](int kt) {
        const int k0 = kt * 64;
        const uint32_t dstB = smub + (kt % 3) * ASTG * 4;
        #pragma unroll
        for (int i = 0; i < 2; i++) {
            const int id  = tid + i * 256;   // 0..511
            const int row = id >> 3, seg = id & 7;
            const uint32_t so = (uint32_t)(row * 144 + seg * 16);
            const size_t g = ((size_t)(b * Ll + k0 + row)) * Dm + hoff + seg * 8;
            CP16(dstB + 0 * APL * 4 + so, Kh + g);
            CP16(dstB + 1 * APL * 4 + so, Kl + g);
            CP16(dstB + 2 * APL * 4 + so, Vh + g);
            CP16(dstB + 3 * APL * 4 + so, Vl + g);
        }
        CP_COMMIT();
    };

    fillKV(0);                                  // group 1 -> stage 0

    asm volatile("cp.async.wait_group 1;" ::: "memory");   // Q done
    __syncthreads();

    // Preload Q fragments (hi + lo)
    uint32_t qh[4][4], ql[4][4];
    {
        const uint32_t* qb = smu + 2 * ASTG + (warp * 16 + r) * AST + cth;
        const uint32_t* qc = qb + AQPL;
        #pragma unroll
        for (int j = 0; j < 4; j++) {
            qh[j][0] = qb[j * 8];
            qh[j][1] = qb[8 * AST + j * 8];
            qh[j][2] = qb[j * 8 + 4];
            qh[j][3] = qb[8 * AST + j * 8 + 4];
            ql[j][0] = qc[j * 8];
            ql[j][1] = qc[8 * AST + j * 8];
            ql[j][2] = qc[j * 8 + 4];
            ql[j][3] = qc[8 * AST + j * 8 + 4];
        }
    }
    __syncthreads();     // everyone done reading Q staging (stage-2 reusable)

    const int ktmax = 2 * qi + 2;
    if (ktmax > 1) fillKV(1);                   // group 2 -> stage 1

    float m_i[2] = {-1e30f, -1e30f};
    float l_i[2] = {0.f, 0.f};
    float o[8][4];
    #pragma unroll
    for (int ni = 0; ni < 8; ni++)
        #pragma unroll
        for (int x = 0; x < 4; x++) o[ni][x] = 0.f;

    for (int kt = 0; kt < ktmax; kt++) {
        if (kt) __syncthreads();                 // all warps done with kt-1
        if (kt + 2 < ktmax) fillKV(kt + 2);      // stage (kt+2)%3 = (kt-1)%3
        else CP_COMMIT();
        asm volatile("cp.async.wait_group 2;" ::: "memory");  // stage kt ready
        if (!kt) __syncthreads();

        const uint32_t stB = smub + (kt % 3) * ASTG * 4;

        // S = (Q/8) K^T  (3-product split-bf16)
        float sacc[8][4];
        #pragma unroll
        for (int ni = 0; ni < 8; ni++)
            #pragma unroll
            for (int x = 0; x < 4; x++) sacc[ni][x] = 0.f;

        #pragma unroll
        for (int j = 0; j < 4; j++) {
            #pragma unroll
            for (int nip = 0; nip < 4; nip++) {
                const uint32_t ka = stB + nip * 2304 + koff + j * 32;
                uint32_t bh[4], bl[4];
                ldsm_x4(bh, ka);
                mma_bf16(sacc[2 * nip],     qh[j], &bh[0]);
                mma_bf16(sacc[2 * nip + 1], qh[j], &bh[2]);
                mma_bf16(sacc[2 * nip],     ql[j], &bh[0]);
                mma_bf16(sacc[2 * nip + 1], ql[j], &bh[2]);
                ldsm_x4(bl, ka + APL * 4);
                mma_bf16(sacc[2 * nip],     qh[j], &bl[0]);
                mma_bf16(sacc[2 * nip + 1], qh[j], &bl[2]);
            }
        }

        const int k0 = kt * 64;
        if (k0 + 63 > q0) {      // causal mask near diagonal
            const int rowb = q0 + warp * 16 + r;
            #pragma unroll
            for (int ni = 0; ni < 8; ni++) {
                const int colb = k0 + ni * 8 + 2 * cth;
                #pragma unroll
                for (int x = 0; x < 4; x++) {
                    const int row = rowb + 8 * (x >> 1);
                    const int col = colb + (x & 1);
                    if (col > row) sacc[ni][x] = -1e30f;
                }
            }
        }

        // online softmax; P packed (bf16 hi/lo) back into sacc as uints
        #pragma unroll
        for (int h = 0; h < 2; h++) {
            float mx = -1e30f;
            #pragma unroll
            for (int ni = 0; ni < 8; ni++)
                mx = fmaxf(mx, fmaxf(sacc[ni][2 * h], sacc[ni][2 * h + 1]));
            mx = fmaxf(mx, __shfl_xor_sync(0xffffffffu, mx, 1));
            mx = fmaxf(mx, __shfl_xor_sync(0xffffffffu, mx, 2));
            const float mnew  = fmaxf(m_i[h], mx);
            const float alpha = __expf(m_i[h] - mnew);
            float sum = 0.f;
            #pragma unroll
            for (int ni = 0; ni < 8; ni++) {
                const float p0 = __expf(sacc[ni][2 * h] - mnew);
                const float p1 = __expf(sacc[ni][2 * h + 1] - mnew);
                sum += p0 + p1;
                uint32_t hv, lv;
                split2(p0, p1, hv, lv);
                sacc[ni][2 * h]     = __uint_as_float(hv);
                sacc[ni][2 * h + 1] = __uint_as_float(lv);
                o[ni][2 * h]     *= alpha;
                o[ni][2 * h + 1] *= alpha;
            }
            sum += __shfl_xor_sync(0xffffffffu, sum, 1);
            sum += __shfl_xor_sync(0xffffffffu, sum, 2);
            l_i[h] = l_i[h] * alpha + sum;
            m_i[h] = mnew;
        }

        // O += P V  (P A-frags direct from registers; V via ldmatrix.trans)
        const uint32_t vB = stB + 2 * APL * 4;
        #pragma unroll
        for (int kk = 0; kk < 4; kk++) {
            uint32_t ph[4], pl[4];
            ph[0] = __float_as_uint(sacc[2 * kk][0]);
            ph[1] = __float_as_uint(sacc[2 * kk][2]);
            ph[2] = __float_as_uint(sacc[2 * kk + 1][0]);
            ph[3] = __float_as_uint(sacc[2 * kk + 1][2]);
            pl[0] = __float_as_uint(sacc[2 * kk][1]);
            pl[1] = __float_as_uint(sacc[2 * kk][3]);
            pl[2] = __float_as_uint(sacc[2 * kk + 1][1]);
            pl[3] = __float_as_uint(sacc[2 * kk + 1][3]);
            #pragma unroll
            for (int nip = 0; nip < 4; nip++) {
                const uint32_t va = vB + kk * 2304 + nip * 32 + voff;
                uint32_t vh[4], vl[4];
                ldsm_x4_t(vh, va);
                mma_bf16(o[2 * nip],     ph, &vh[0]);
                mma_bf16(o[2 * nip + 1], ph, &vh[2]);
                mma_bf16(o[2 * nip],     pl, &vh[0]);
                mma_bf16(o[2 * nip + 1], pl, &vh[2]);
                ldsm_x4_t(vl, va + APL * 4);
                mma_bf16(o[2 * nip],     ph, &vl[0]);
                mma_bf16(o[2 * nip + 1], ph, &vl[2]);
            }
        }
    }

    // normalize + split + write context planes
    #pragma unroll
    for (int h = 0; h < 2; h++) {
        const float inv = 1.0f / l_i[h];
        const int row = q0 + warp * 16 + r + 8 * h;
        const size_t base = ((size_t)(b * Ll + row)) * (Dm / 2) + hd * 32;
        #pragma unroll
        for (int ni = 0; ni < 8; ni++) {
            uint32_t hv, lv;
            split2(o[ni][2 * h] * inv, o[ni][2 * h + 1] * inv, hv, lv);
            ((uint32_t*)Ch)[base + ni * 4 + cth] = hv;
            ((uint32_t*)Cl)[base + ni * 4 + cth] = lv;
        }
    }
}

// ---------------------------------------------------------------------------
extern "C" void kernel_launch(void* const* d_in, const int* in_sizes, int n_in,
                              void* d_out, int out_size)
{
    const float* q    = (const float*)d_in[0];
    const float* k    = (const float*)d_in[1];
    const float* v    = (const float*)d_in[2];
    const float* wq_w = (const float*)d_in[3];
    const float* wq_b = (const float*)d_in[4];
    const float* wk_w = (const float*)d_in[5];
    const float* wk_b = (const float*)d_in[6];
    const float* wv_w = (const float*)d_in[7];
    const float* wv_b = (const float*)d_in[8];
    const float* wo_w = (const float*)d_in[9];
    const float* wo_b = (const float*)d_in[10];
    float* out = (float*)d_out;

    uint16_t* P;
    cudaGetSymbolAddress((void**)&P, g_buf);
    uint16_t* W = P + 14 * NPLANE;
    #define PLN(i) (P + (size_t)(i) * NPLANE)
    #define WPL(i) (W + (size_t)(i) * WPLANE)

    cudaFuncSetAttribute(gemm_bf16s, cudaFuncAttributeMaxDynamicSharedMemorySize,
                         GEMM_SMEM_BYTES);
    cudaFuncSetAttribute(attn_bf16s, cudaFuncAttributeMaxDynamicSharedMemorySize,
                         ATT_SMEM_BYTES);

    const int n8a = (int)(NPLANE / 8);   // 1048576
    const int n8w = (int)(WPLANE / 8);   // 131072

    Split4 sa;
    sa.in[0] = q; sa.hi[0] = PLN(0); sa.lo[0] = PLN(1);
    sa.in[1] = k; sa.hi[1] = PLN(2); sa.lo[1] = PLN(3);
    sa.in[2] = v; sa.hi[2] = PLN(4); sa.lo[2] = PLN(5);
    sa.in[3] = q; sa.hi[3] = PLN(0); sa.lo[3] = PLN(1);  // unused
    dim3 gs(n8a / 256, 3);
    split_multi<<<gs, 256>>>(sa, n8a);

    Split4 sw;
    sw.in[0] = wq_w; sw.hi[0] = WPL(0); sw.lo[0] = WPL(1);
    sw.in[1] = wk_w; sw.hi[1] = WPL(2); sw.lo[1] = WPL(3);
    sw.in[2] = wv_w; sw.hi[2] = WPL(4); sw.lo[2] = WPL(5);
    sw.in[3] = wo_w; sw.hi[3] = WPL(6); sw.lo[3] = WPL(7);
    dim3 gw(n8w / 256, 4);
    split_multi<<<gw, 256>>>(sw, n8w);

    // fused Q/K/V projections (Q pre-scaled by 1/8)
    GemmBatch proj;
    proj.j[0] = {PLN(0), PLN(1), WPL(0), WPL(1), wq_b, nullptr, PLN(6), PLN(7), 0.125f};
    proj.j[1] = {PLN(2), PLN(3), WPL(2), WPL(3), wk_b, nullptr, PLN(8), PLN(9), 1.0f};
    proj.j[2] = {PLN(4), PLN(5), WPL(4), WPL(5), wv_b, nullptr, PLN(10), PLN(11), 1.0f};
    dim3 gg(GN / 128, MTOT / 128, 3);   // (8, 64, 3)
    gemm_bf16s<<<gg, 256, GEMM_SMEM_BYTES>>>(proj);

    dim3 ga(Ll / 128, Hh, Bb);          // (16, 16, 4)
    attn_bf16s<<<ga, 256, ATT_SMEM_BYTES>>>(PLN(6), PLN(7), PLN(8), PLN(9),
                                            PLN(10), PLN(11), PLN(12), PLN(13));

    // output projection -> fp32 out
    GemmBatch outp;
    outp.j[0] = {PLN(12), PLN(13), WPL(6), WPL(7), wo_b, out, nullptr, nullptr, 1.0f};
    outp.j[1] = outp.j[0];
    outp.j[2] = outp.j[0];
    dim3 go(GN / 128, MTOT / 128, 1);
    gemm_bf16s<<<go, 256, GEMM_SMEM_BYTES>>>(outp);
    #undef PLN
    #undef WPL
}

// round 10
// speedup vs baseline: 1.0220x; 1.0220x over previous
#include <cuda_runtime.h>
#include <math.h>
#include <stdint.h>

#define Dm   1024
#define Hh   16
#define DKk  64
#define Bb   4
#define Ll   2048
#define MTOT (Bb * Ll)   // 8192

#define NPLANE ((size_t)MTOT * Dm)   // 8388608 elems
#define WPLANE ((size_t)Dm * Dm)     // 1048576

// One big bf16 scratch buffer (no allocations allowed): 240 MB
__device__ __align__(16) uint16_t g_buf[14 * NPLANE + 8 * WPLANE];

__device__ __forceinline__ uint32_t smem_u32(const void* p) {
    uint32_t a;
    asm("{ .reg .u64 t; cvta.to.shared.u64 t, %1; cvt.u32.u64 %0, t; }"
        : "=r"(a) : "l"(p));
    return a;
}

// Split two fp32 into packed bf16 hi-pair and lo-pair (x0 -> low half).
__device__ __forceinline__ void split2(float x0, float x1,
                                       uint32_t& hi, uint32_t& lo) {
    uint32_t h;
    asm("cvt.rn.bf16x2.f32 %0, %1, %2;" : "=r"(h) : "f"(x1), "f"(x0));
    const float f0 = __uint_as_float(h << 16);
    const float f1 = __uint_as_float(h & 0xffff0000u);
    uint32_t l;
    asm("cvt.rn.bf16x2.f32 %0, %1, %2;" : "=r"(l) : "f"(x1 - f1), "f"(x0 - f0));
    hi = h; lo = l;
}

__device__ __forceinline__ void mma_bf16(float d[4], const uint32_t a[4],
                                         const uint32_t b[2]) {
    asm volatile(
        "mma.sync.aligned.m16n8k16.row.col.f32.bf16.bf16.f32 "
        "{%0,%1,%2,%3}, {%4,%5,%6,%7}, {%8,%9}, {%0,%1,%2,%3};"
        : "+f"(d[0]), "+f"(d[1]), "+f"(d[2]), "+f"(d[3])
        : "r"(a[0]), "r"(a[1]), "r"(a[2]), "r"(a[3]), "r"(b[0]), "r"(b[1]));
}

__device__ __forceinline__ void ldsm_x4(uint32_t r[4], uint32_t a) {
    asm volatile("ldmatrix.sync.aligned.m8n8.x4.shared.b16 {%0,%1,%2,%3}, [%4];"
                 : "=r"(r[0]), "=r"(r[1]), "=r"(r[2]), "=r"(r[3]) : "r"(a));
}
__device__ __forceinline__ void ldsm_x4_t(uint32_t r[4], uint32_t a) {
    asm volatile("ldmatrix.sync.aligned.m8n8.x4.trans.shared.b16 {%0,%1,%2,%3}, [%4];"
                 : "=r"(r[0]), "=r"(r[1]), "=r"(r[2]), "=r"(r[3]) : "r"(a));
}

#define CP16(smaddr, gptr) \
    asm volatile("cp.async.cg.shared.global [%0], [%1], 16;" \
                 :: "r"(smaddr), "l"(gptr))
#define CP_COMMIT() asm volatile("cp.async.commit_group;")

// ---------------------------------------------------------------------------
// fp32 -> bf16 hi/lo plane split, up to 4 tensors per launch (blockIdx.y)
// ---------------------------------------------------------------------------
struct Split4 {
    const float* in[4];
    uint16_t* hi[4];
    uint16_t* lo[4];
};

__global__ __launch_bounds__(256)
void split_multi(Split4 a, int n8)
{
    const float* in = a.in[blockIdx.y];
    uint16_t* hi = a.hi[blockIdx.y];
    uint16_t* lo = a.lo[blockIdx.y];
    const int i = blockIdx.x * 256 + threadIdx.x;
    if (i < n8) {
        const float4* in4 = (const float4*)in;
        float4 x = in4[2 * i], y = in4[2 * i + 1];
        uint4 H, L;
        split2(x.x, x.y, H.x, L.x);
        split2(x.z, x.w, H.y, L.y);
        split2(y.x, y.y, H.z, L.z);
        split2(y.z, y.w, H.w, L.w);
        ((uint4*)hi)[i] = H;
        ((uint4*)lo)[i] = L;
    }
}

// ---------------------------------------------------------------------------
// split-bf16 GEMM (batched over blockIdx.z): C = A @ W^T + bias.
// 128 thr / 4 warps (2m x 2n), WARP TILE 64x64 (MMA:ldsm ratio 6),
// KCH=16, 4-stage cp.async pipeline. 2 CTAs/SM -> 256-reg budget.
// ---------------------------------------------------------------------------
#define GK      1024
#define GN      1024
#define KCH     16
#define NCHUNK  (GK / KCH)             // 64
#define GROWB   48                     // bytes per smem row (32 B data)
#define GPLANEB (128 * GROWB)          // 6144 B per plane
#define GSTAGEB (4 * GPLANEB)          // 24576 B (Ahi,Alo,Bhi,Blo)
#define GEMM_SMEM_BYTES (4 * GSTAGEB)  // 98304 B

struct GemmJob {
    const uint16_t *Ah, *Al, *Bh, *Bl;
    const float* bias;
    float* Cf;           // fp32 output (or null)
    uint16_t *Ch, *Cl;   // bf16 plane outputs (if Cf null)
    float scale;
};
struct GemmBatch { GemmJob j[3]; };

__global__ __launch_bounds__(128, 2)
void gemm_bf16s(GemmBatch batch)
{
    extern __shared__ uint32_t smu[];
    const GemmJob jb = batch.j[blockIdx.z];

    const int tid  = threadIdx.x;
    const int warp = tid >> 5;
    const int lane = tid & 31;
    const int wm   = warp & 1;
    const int wn   = warp >> 1;        // 0..1
    const int m0   = blockIdx.y * 128;
    const int n0   = blockIdx.x * 128;

    const uint32_t smub = smem_u32(smu);
    const uint32_t aoff = (uint32_t)(((lane & 7) + ((lane >> 3) & 1) * 8) * GROWB +
                                     ((lane >> 4) << 4));
    const uint32_t boff = (uint32_t)(((lane & 7) + ((lane >> 4) << 3)) * GROWB +
                                     (((lane >> 3) & 1) << 4));

    float d[4][8][4];
    #pragma unroll
    for (int mi = 0; mi < 4; mi++)
        #pragma unroll
        for (int ni = 0; ni < 8; ni++)
            #pragma unroll
            for (int x = 0; x < 4; x++) d[mi][ni][x] = 0.f;

    auto fill = [&](int c) {
        const int k0 = c * KCH;
        const uint32_t base = smub + (c & 3) * GSTAGEB;
        const size_t ga = (size_t)(m0 + tid) * GK + k0;
        const size_t gb = (size_t)(n0 + tid) * GK + k0;
        const uint32_t so = (uint32_t)(tid * GROWB);
        #pragma unroll
        for (int seg = 0; seg < 2; seg++) {
            CP16(base + 0 * GPLANEB + so + seg * 16, jb.Ah + ga + seg * 8);
            CP16(base + 1 * GPLANEB + so + seg * 16, jb.Al + ga + seg * 8);
            CP16(base + 2 * GPLANEB + so + seg * 16, jb.Bh + gb + seg * 8);
            CP16(base + 3 * GPLANEB + so + seg * 16, jb.Bl + gb + seg * 8);
        }
        CP_COMMIT();
    };

    fill(0); fill(1); fill(2);

    for (int c = 0; c < NCHUNK; c++) {
        if (c) __syncthreads();
        if (c + 3 < NCHUNK) fill(c + 3);
        else CP_COMMIT();
        asm volatile("cp.async.wait_group 3;" ::: "memory");
        if (!c) __syncthreads();

        const uint32_t stB = smub + (c & 3) * GSTAGEB;
        const uint32_t aA  = stB + (uint32_t)(wm * 64 * GROWB) + aoff;
        const uint32_t aB  = stB + 2 * GPLANEB + (uint32_t)(wn * 64 * GROWB) + boff;

        uint32_t ah[4][4], bh[4][4], bl[4][4];
        #pragma unroll
        for (int mi = 0; mi < 4; mi++)
            ldsm_x4(ah[mi], aA + mi * 16 * GROWB);
        #pragma unroll
        for (int p = 0; p < 4; p++)
            ldsm_x4(bh[p], aB + p * 16 * GROWB);
        // product 1: Ah*Bh
        #pragma unroll
        for (int mi = 0; mi < 4; mi++)
            #pragma unroll
            for (int p = 0; p < 4; p++) {
                mma_bf16(d[mi][2 * p],     ah[mi], &bh[p][0]);
                mma_bf16(d[mi][2 * p + 1], ah[mi], &bh[p][2]);
            }
        // product 2: Ah*Bl
        #pragma unroll
        for (int p = 0; p < 4; p++)
            ldsm_x4(bl[p], aB + GPLANEB + p * 16 * GROWB);
        #pragma unroll
        for (int mi = 0; mi < 4; mi++)
            #pragma unroll
            for (int p = 0; p < 4; p++) {
                mma_bf16(d[mi][2 * p],     ah[mi], &bl[p][0]);
                mma_bf16(d[mi][2 * p + 1], ah[mi], &bl[p][2]);
            }
        // product 3: Al*Bh (reuse ah regs)
        #pragma unroll
        for (int mi = 0; mi < 4; mi++)
            ldsm_x4(ah[mi], aA + GPLANEB + mi * 16 * GROWB);
        #pragma unroll
        for (int mi = 0; mi < 4; mi++)
            #pragma unroll
            for (int p = 0; p < 4; p++) {
                mma_bf16(d[mi][2 * p],     ah[mi], &bh[p][0]);
                mma_bf16(d[mi][2 * p + 1], ah[mi], &bh[p][2]);
            }
    }

    const int row0 = m0 + wm * 64 + (lane >> 2);
    const int colb = n0 + wn * 64 + 2 * (lane & 3);
    #pragma unroll
    for (int ni = 0; ni < 8; ni++) {
        const int c = colb + ni * 8;
        const float b0 = jb.bias[c], b1 = jb.bias[c + 1];
        #pragma unroll
        for (int mi = 0; mi < 4; mi++) {
            #pragma unroll
            for (int half = 0; half < 2; half++) {
                const int r = row0 + mi * 16 + 8 * half;
                const float v0 = d[mi][ni][2 * half]     + b0;
                const float v1 = d[mi][ni][2 * half + 1] + b1;
                if (jb.Cf) {
                    float2 w = {v0, v1};
                    *(float2*)(jb.Cf + (size_t)r * GN + c) = w;
                } else {
                    uint32_t hv, lv;
                    split2(v0 * jb.scale, v1 * jb.scale, hv, lv);
                    ((uint32_t*)jb.Ch)[(size_t)r * (GN / 2) + c / 2] = hv;
                    ((uint32_t*)jb.Cl)[(size_t)r * (GN / 2) + c / 2] = lv;
                }
            }
        }
    }
}

// ---------------------------------------------------------------------------
// Flash attention (causal), split-bf16. 128 thr / 4 warps; each warp owns
// 32 q-rows (two m16 blocks) x 64 keys -> every K/V ldsm feeds 12 MMAs.
// P kept in registers. 3-stage KV pipeline; Q staged through stage 2.
// ---------------------------------------------------------------------------
#define AST     36                  // u32 per row (144 B)
#define APL     (64 * AST)          // KV plane u32 (2304)
#define ASTG    (4 * APL)           // stage u32 (9216)
#define AQPL    (128 * AST)         // Q plane u32 (4608)
#define ATT_SMEM_BYTES (3 * ASTG * 4)   // 110592

__global__ __launch_bounds__(128, 2)
void attn_bf16s(const uint16_t* __restrict__ Qh, const uint16_t* __restrict__ Ql,
                const uint16_t* __restrict__ Kh, const uint16_t* __restrict__ Kl,
                const uint16_t* __restrict__ Vh, const uint16_t* __restrict__ Vl,
                uint16_t* __restrict__ Ch, uint16_t* __restrict__ Cl)
{
    extern __shared__ uint32_t smu[];
    const int tid  = threadIdx.x;
    const int lane = tid & 31;
    const int warp = tid >> 5;          // 0..3
    const int r    = lane >> 2;
    const int cth  = lane & 3;
    const int qi   = gridDim.x - 1 - blockIdx.x;   // heavy tiles first
    const int hd   = blockIdx.y;
    const int b    = blockIdx.z;
    const int q0   = qi * 128;

    const uint32_t smub = smem_u32(smu);
    const size_t hoff = (size_t)hd * 64;

    const uint32_t koff = (uint32_t)(((lane & 7) + ((lane >> 4) << 3)) * 144 +
                                     (((lane >> 3) & 1) << 4));
    const uint32_t voff = (uint32_t)((lane & 15) * 144 + ((lane >> 4) << 4));

    // Prologue: Q planes into stage-2 area (group 0)
    #pragma unroll
    for (int i = 0; i < 8; i++) {
        const int id  = tid + i * 128;       // 0..1023
        const int row = id >> 3, seg = id & 7;
        const uint32_t so = (uint32_t)(row * 144 + seg * 16);
        const size_t g = ((size_t)(b * Ll + q0 + row)) * Dm + hoff + seg * 8;
        CP16(smub + 2 * ASTG * 4 + so, Qh + g);
        CP16(smub + 2 * ASTG * 4 + AQPL * 4 + so, Ql + g);
    }
    CP_COMMIT();

    auto fillKV = [&](int kt) {
        const int k0 = kt * 64;
        const uint32_t dstB = smub + (kt % 3) * ASTG * 4;
        #pragma unroll
        for (int i = 0; i < 4; i++) {
            const int id  = tid + i * 128;   // 0..511
            const int row = id >> 3, seg = id & 7;
            const uint32_t so = (uint32_t)(row * 144 + seg * 16);
            const size_t g = ((size_t)(b * Ll + k0 + row)) * Dm + hoff + seg * 8;
            CP16(dstB + 0 * APL * 4 + so, Kh + g);
            CP16(dstB + 1 * APL * 4 + so, Kl + g);
            CP16(dstB + 2 * APL * 4 + so, Vh + g);
            CP16(dstB + 3 * APL * 4 + so, Vl + g);
        }
        CP_COMMIT();
    };

    fillKV(0);                                  // group 1 -> stage 0

    asm volatile("cp.async.wait_group 1;" ::: "memory");   // Q done
    __syncthreads();

    // Preload Q fragments for both m16 blocks (hi + lo)
    uint32_t qh[2][4][4], ql[2][4][4];
    #pragma unroll
    for (int g = 0; g < 2; g++) {
        const uint32_t* qb = smu + 2 * ASTG + (warp * 32 + g * 16 + r) * AST + cth;
        const uint32_t* qc = qb + AQPL;
        #pragma unroll
        for (int j = 0; j < 4; j++) {
            qh[g][j][0] = qb[j * 8];
            qh[g][j][1] = qb[8 * AST + j * 8];
            qh[g][j][2] = qb[j * 8 + 4];
            qh[g][j][3] = qb[8 * AST + j * 8 + 4];
            ql[g][j][0] = qc[j * 8];
            ql[g][j][1] = qc[8 * AST + j * 8];
            ql[g][j][2] = qc[j * 8 + 4];
            ql[g][j][3] = qc[8 * AST + j * 8 + 4];
        }
    }
    __syncthreads();     // Q staging (stage-2) reusable

    const int ktmax = 2 * qi + 2;
    if (ktmax > 1) fillKV(1);                   // group 2 -> stage 1

    float m_i[2][2], l_i[2][2];
    #pragma unroll
    for (int g = 0; g < 2; g++)
        #pragma unroll
        for (int h = 0; h < 2; h++) { m_i[g][h] = -1e30f; l_i[g][h] = 0.f; }
    float o[2][8][4];
    #pragma unroll
    for (int g = 0; g < 2; g++)
        #pragma unroll
        for (int ni = 0; ni < 8; ni++)
            #pragma unroll
            for (int x = 0; x < 4; x++) o[g][ni][x] = 0.f;

    for (int kt = 0; kt < ktmax; kt++) {
        if (kt) __syncthreads();                 // all warps done with kt-1
        if (kt + 2 < ktmax) fillKV(kt + 2);
        else CP_COMMIT();
        asm volatile("cp.async.wait_group 2;" ::: "memory");  // stage kt ready
        if (!kt) __syncthreads();

        const uint32_t stB = smub + (kt % 3) * ASTG * 4;

        // S = (Q/8) K^T  (3-product split-bf16; K ldsm shared by both g)
        float sacc[2][8][4];
        #pragma unroll
        for (int g = 0; g < 2; g++)
            #pragma unroll
            for (int ni = 0; ni < 8; ni++)
                #pragma unroll
                for (int x = 0; x < 4; x++) sacc[g][ni][x] = 0.f;

        #pragma unroll
        for (int j = 0; j < 4; j++) {
            #pragma unroll
            for (int nip = 0; nip < 4; nip++) {
                const uint32_t ka = stB + nip * 2304 + koff + j * 32;
                uint32_t bh[4], bl[4];
                ldsm_x4(bh, ka);
                #pragma unroll
                for (int g = 0; g < 2; g++) {
                    mma_bf16(sacc[g][2 * nip],     qh[g][j], &bh[0]);
                    mma_bf16(sacc[g][2 * nip + 1], qh[g][j], &bh[2]);
                    mma_bf16(sacc[g][2 * nip],     ql[g][j], &bh[0]);
                    mma_bf16(sacc[g][2 * nip + 1], ql[g][j], &bh[2]);
                }
                ldsm_x4(bl, ka + APL * 4);
                #pragma unroll
                for (int g = 0; g < 2; g++) {
                    mma_bf16(sacc[g][2 * nip],     qh[g][j], &bl[0]);
                    mma_bf16(sacc[g][2 * nip + 1], qh[g][j], &bl[2]);
                }
            }
        }

        const int k0 = kt * 64;
        if (k0 + 63 > q0) {      // causal mask near diagonal
            #pragma unroll
            for (int g = 0; g < 2; g++) {
                const int rowb = q0 + warp * 32 + g * 16 + r;
                #pragma unroll
                for (int ni = 0; ni < 8; ni++) {
                    const int colb = k0 + ni * 8 + 2 * cth;
                    #pragma unroll
                    for (int x = 0; x < 4; x++) {
                        const int row = rowb + 8 * (x >> 1);
                        const int col = colb + (x & 1);
                        if (col > row) sacc[g][ni][x] = -1e30f;
                    }
                }
            }
        }

        // online softmax; P packed (bf16 hi/lo) back into sacc as uints
        #pragma unroll
        for (int g = 0; g < 2; g++)
            #pragma unroll
            for (int h = 0; h < 2; h++) {
                float mx = -1e30f;
                #pragma unroll
                for (int ni = 0; ni < 8; ni++)
                    mx = fmaxf(mx, fmaxf(sacc[g][ni][2 * h], sacc[g][ni][2 * h + 1]));
                mx = fmaxf(mx, __shfl_xor_sync(0xffffffffu, mx, 1));
                mx = fmaxf(mx, __shfl_xor_sync(0xffffffffu, mx, 2));
                const float mnew  = fmaxf(m_i[g][h], mx);
                const float alpha = __expf(m_i[g][h] - mnew);
                float sum = 0.f;
                #pragma unroll
                for (int ni = 0; ni < 8; ni++) {
                    const float p0 = __expf(sacc[g][ni][2 * h] - mnew);
                    const float p1 = __expf(sacc[g][ni][2 * h + 1] - mnew);
                    sum += p0 + p1;
                    uint32_t hv, lv;
                    split2(p0, p1, hv, lv);
                    sacc[g][ni][2 * h]     = __uint_as_float(hv);
                    sacc[g][ni][2 * h + 1] = __uint_as_float(lv);
                    o[g][ni][2 * h]     *= alpha;
                    o[g][ni][2 * h + 1] *= alpha;
                }
                sum += __shfl_xor_sync(0xffffffffu, sum, 1);
                sum += __shfl_xor_sync(0xffffffffu, sum, 2);
                l_i[g][h] = l_i[g][h] * alpha + sum;
                m_i[g][h] = mnew;
            }

        // O += P V  (P A-frags from registers; V ldsm shared by both g)
        const uint32_t vB = stB + 2 * APL * 4;
        #pragma unroll
        for (int kk = 0; kk < 4; kk++) {
            uint32_t ph[2][4], pl[2][4];
            #pragma unroll
            for (int g = 0; g < 2; g++) {
                ph[g][0] = __float_as_uint(sacc[g][2 * kk][0]);
                ph[g][1] = __float_as_uint(sacc[g][2 * kk][2]);
                ph[g][2] = __float_as_uint(sacc[g][2 * kk + 1][0]);
                ph[g][3] = __float_as_uint(sacc[g][2 * kk + 1][2]);
                pl[g][0] = __float_as_uint(sacc[g][2 * kk][1]);
                pl[g][1] = __float_as_uint(sacc[g][2 * kk][3]);
                pl[g][2] = __float_as_uint(sacc[g][2 * kk + 1][1]);
                pl[g][3] = __float_as_uint(sacc[g][2 * kk + 1][3]);
            }
            #pragma unroll
            for (int nip = 0; nip < 4; nip++) {
                const uint32_t va = vB + kk * 2304 + nip * 32 + voff;
                uint32_t vh[4], vl[4];
                ldsm_x4_t(vh, va);
                #pragma unroll
                for (int g = 0; g < 2; g++) {
                    mma_bf16(o[g][2 * nip],     ph[g], &vh[0]);
                    mma_bf16(o[g][2 * nip + 1], ph[g], &vh[2]);
                    mma_bf16(o[g][2 * nip],     pl[g], &vh[0]);
                    mma_bf16(o[g][2 * nip + 1], pl[g], &vh[2]);
                }
                ldsm_x4_t(vl, va + APL * 4);
                #pragma unroll
                for (int g = 0; g < 2; g++) {
                    mma_bf16(o[g][2 * nip],     ph[g], &vl[0]);
                    mma_bf16(o[g][2 * nip + 1], ph[g], &vl[2]);
                }
            }
        }
    }

    // normalize + split + write context planes
    #pragma unroll
    for (int g = 0; g < 2; g++)
        #pragma unroll
        for (int h = 0; h < 2; h++) {
            const float inv = 1.0f / l_i[g][h];
            const int row = q0 + warp * 32 + g * 16 + r + 8 * h;
            const size_t base = ((size_t)(b * Ll + row)) * (Dm / 2) + hd * 32;
            #pragma unroll
            for (int ni = 0; ni < 8; ni++) {
                uint32_t hv, lv;
                split2(o[g][ni][2 * h] * inv, o[g][ni][2 * h + 1] * inv, hv, lv);
                ((uint32_t*)Ch)[base + ni * 4 + cth] = hv;
                ((uint32_t*)Cl)[base + ni * 4 + cth] = lv;
            }
        }
}

// ---------------------------------------------------------------------------
extern "C" void kernel_launch(void* const* d_in, const int* in_sizes, int n_in,
                              void* d_out, int out_size)
{
    const float* q    = (const float*)d_in[0];
    const float* k    = (const float*)d_in[1];
    const float* v    = (const float*)d_in[2];
    const float* wq_w = (const float*)d_in[3];
    const float* wq_b = (const float*)d_in[4];
    const float* wk_w = (const float*)d_in[5];
    const float* wk_b = (const float*)d_in[6];
    const float* wv_w = (const float*)d_in[7];
    const float* wv_b = (const float*)d_in[8];
    const float* wo_w = (const float*)d_in[9];
    const float* wo_b = (const float*)d_in[10];
    float* out = (float*)d_out;

    uint16_t* P;
    cudaGetSymbolAddress((void**)&P, g_buf);
    uint16_t* W = P + 14 * NPLANE;
    #define PLN(i) (P + (size_t)(i) * NPLANE)
    #define WPL(i) (W + (size_t)(i) * WPLANE)

    cudaFuncSetAttribute(gemm_bf16s, cudaFuncAttributeMaxDynamicSharedMemorySize,
                         GEMM_SMEM_BYTES);
    cudaFuncSetAttribute(attn_bf16s, cudaFuncAttributeMaxDynamicSharedMemorySize,
                         ATT_SMEM_BYTES);

    const int n8a = (int)(NPLANE / 8);   // 1048576
    const int n8w = (int)(WPLANE / 8);   // 131072

    Split4 sa;
    sa.in[0] = q; sa.hi[0] = PLN(0); sa.lo[0] = PLN(1);
    sa.in[1] = k; sa.hi[1] = PLN(2); sa.lo[1] = PLN(3);
    sa.in[2] = v; sa.hi[2] = PLN(4); sa.lo[2] = PLN(5);
    sa.in[3] = q; sa.hi[3] = PLN(0); sa.lo[3] = PLN(1);  // unused
    dim3 gs(n8a / 256, 3);
    split_multi<<<gs, 256>>>(sa, n8a);

    Split4 sw;
    sw.in[0] = wq_w; sw.hi[0] = WPL(0); sw.lo[0] = WPL(1);
    sw.in[1] = wk_w; sw.hi[1] = WPL(2); sw.lo[1] = WPL(3);
    sw.in[2] = wv_w; sw.hi[2] = WPL(4); sw.lo[2] = WPL(5);
    sw.in[3] = wo_w; sw.hi[3] = WPL(6); sw.lo[3] = WPL(7);
    dim3 gw(n8w / 256, 4);
    split_multi<<<gw, 256>>>(sw, n8w);

    // fused Q/K/V projections (Q pre-scaled by 1/8)
    GemmBatch proj;
    proj.j[0] = {PLN(0), PLN(1), WPL(0), WPL(1), wq_b, nullptr, PLN(6), PLN(7), 0.125f};
    proj.j[1] = {PLN(2), PLN(3), WPL(2), WPL(3), wk_b, nullptr, PLN(8), PLN(9), 1.0f};
    proj.j[2] = {PLN(4), PLN(5), WPL(4), WPL(5), wv_b, nullptr, PLN(10), PLN(11), 1.0f};
    dim3 gg(GN / 128, MTOT / 128, 3);   // (8, 64, 3)
    gemm_bf16s<<<gg, 128, GEMM_SMEM_BYTES>>>(proj);

    dim3 ga(Ll / 128, Hh, Bb);          // (16, 16, 4)
    attn_bf16s<<<ga, 128, ATT_SMEM_BYTES>>>(PLN(6), PLN(7), PLN(8), PLN(9),
                                            PLN(10), PLN(11), PLN(12), PLN(13));

    // output projection -> fp32 out
    GemmBatch outp;
    outp.j[0] = {PLN(12), PLN(13), WPL(6), WPL(7), wo_b, out, nullptr, nullptr, 1.0f};
    outp.j[1] = outp.j[0];
    outp.j[2] = outp.j[0];
    dim3 go(GN / 128, MTOT / 128, 1);
    gemm_bf16s<<<go, 128, GEMM_SMEM_BYTES>>>(outp);
    #undef PLN
    #undef WPL
}